// round 1
// baseline (speedup 1.0000x reference)
#include <cuda_runtime.h>

// ---------------------------------------------------------------------------
// HgnnEncoder: 3-layer hypergraph conv
//   per layer:  Ae = B^-1 H^T X   (edge aggregation, F_in)
//               Ge = Ae @ W + b   (GEMM on 10000 edge rows only)
//               out = relu(D^-1 H Ge)  (node aggregation, F_out)
// CSR built per launch (deterministic up to fp-sum order; no float atomics).
// ---------------------------------------------------------------------------

#define NNZ  800000
#define N_V  50000
#define N_E  10000

__device__ int   g_is64;
__device__ int   g_deg_e[N_E];
__device__ int   g_deg_v[N_V];
__device__ int   g_cur_e[N_E];
__device__ int   g_cur_v[N_V];
__device__ int   g_off_e[N_E + 1];
__device__ int   g_off_v[N_V + 1];
__device__ int   g_adj_e[NNZ];     // grouped by hyperedge, stores node ids
__device__ int   g_adj_v[NNZ];     // grouped by node, stores hyperedge ids
__device__ float g_Binv[N_E];
__device__ float g_Dinv[N_V];
__device__ float g_Ae[N_E * 128];
__device__ float g_Ge[N_E * 128];
__device__ float g_h1[(size_t)N_V * 128];
__device__ float g_h2[(size_t)N_V * 64];

// ---------------------------------------------------------------------------
__global__ void k_zero() {
    int stride = gridDim.x * blockDim.x;
    int i = blockIdx.x * blockDim.x + threadIdx.x;
    for (int j = i; j < N_E; j += stride) { g_deg_e[j] = 0; g_cur_e[j] = 0; }
    for (int j = i; j < N_V; j += stride) { g_deg_v[j] = 0; g_cur_v[j] = 0; }
}

// Detect whether the edge buffer is int64 or int32. Values are < 10000, so if
// int64 (little-endian), every odd 32-bit word of the first 8192 words is 0.
// For int32 data the odd words are uniform [0,10000): P(all zero) ~ 0.
__global__ void k_detect(const unsigned int* __restrict__ e32) {
    __shared__ int any;
    if (threadIdx.x == 0) any = 0;
    __syncthreads();
    unsigned int local = 0;
    for (int i = 1 + 2 * threadIdx.x; i < 8192; i += 2 * blockDim.x)
        local |= e32[i];
    if (local) any = 1;
    __syncthreads();
    if (threadIdx.x == 0) g_is64 = any ? 0 : 1;
}

__device__ __forceinline__ int load_idx(const void* edge, int i, int is64) {
    if (is64) return (int)((const long long*)edge)[i];
    return ((const int*)edge)[i];
}

__global__ void k_hist(const void* __restrict__ edge) {
    int is64 = g_is64;
    int stride = gridDim.x * blockDim.x;
    for (int i = blockIdx.x * blockDim.x + threadIdx.x; i < NNZ; i += stride) {
        int v = load_idx(edge, i, is64);
        int e = load_idx(edge, NNZ + i, is64);
        atomicAdd(&g_deg_v[v], 1);
        atomicAdd(&g_deg_e[e], 1);
    }
}

__global__ void k_inv() {
    int i = blockIdx.x * blockDim.x + threadIdx.x;
    if (i < N_E) { int d = g_deg_e[i]; g_Binv[i] = d ? 1.0f / (float)d : 0.0f; }
    if (i < N_V) { int d = g_deg_v[i]; g_Dinv[i] = d ? 1.0f / (float)d : 0.0f; }
}

// Single-block shuffle-based inclusive scan -> exclusive offsets.
// EDGES=true scans deg_e into off_e, else deg_v into off_v.
template <bool EDGES>
__global__ void k_scan() {
    const int n = EDGES ? N_E : N_V;
    const int* __restrict__ deg = EDGES ? g_deg_e : g_deg_v;
    int* __restrict__ off = EDGES ? g_off_e : g_off_v;

    __shared__ int wsum[32];
    __shared__ int s_carry;
    int tid = threadIdx.x, lane = tid & 31, wid = tid >> 5;
    if (tid == 0) { s_carry = 0; off[0] = 0; }
    __syncthreads();
    for (int base = 0; base < n; base += 1024) {
        int i = base + tid;
        int x = (i < n) ? deg[i] : 0;
#pragma unroll
        for (int d = 1; d < 32; d <<= 1) {
            int t = __shfl_up_sync(0xffffffffu, x, d);
            if (lane >= d) x += t;
        }
        if (lane == 31) wsum[wid] = x;
        __syncthreads();
        if (wid == 0) {
            int y = wsum[lane];
#pragma unroll
            for (int d = 1; d < 32; d <<= 1) {
                int t = __shfl_up_sync(0xffffffffu, y, d);
                if (lane >= d) y += t;
            }
            wsum[lane] = y;
        }
        __syncthreads();
        int warpoff = (wid == 0) ? 0 : wsum[wid - 1];
        int carry = s_carry;
        if (i < n) off[i + 1] = x + warpoff + carry;
        __syncthreads();
        if (tid == 1023) s_carry = carry + wsum[31];
        __syncthreads();
    }
}

__global__ void k_scatter(const void* __restrict__ edge) {
    int is64 = g_is64;
    int stride = gridDim.x * blockDim.x;
    for (int i = blockIdx.x * blockDim.x + threadIdx.x; i < NNZ; i += stride) {
        int v = load_idx(edge, i, is64);
        int e = load_idx(edge, NNZ + i, is64);
        int pe = atomicAdd(&g_cur_e[e], 1);
        g_adj_e[g_off_e[e] + pe] = v;
        int pv = atomicAdd(&g_cur_v[v], 1);
        g_adj_v[g_off_v[v] + pv] = e;
    }
}

// ---------------------------------------------------------------------------
// Edge aggregation: Ae[e][f] = Binv[e] * sum_{v in e} X[v][f]
// One edge per (threadIdx.y); F threads across features, 128 threads/block.
template <int F>
__global__ void k_edge_agg(const float* __restrict__ X) {
    int e = blockIdx.x * (128 / F) + threadIdx.y;
    if (e >= N_E) return;
    int f = threadIdx.x;
    int s = g_off_e[e], t = g_off_e[e + 1];
    float a0 = 0.f, a1 = 0.f, a2 = 0.f, a3 = 0.f;
    int m = s;
    for (; m + 4 <= t; m += 4) {
        int i0 = g_adj_e[m + 0], i1 = g_adj_e[m + 1];
        int i2 = g_adj_e[m + 2], i3 = g_adj_e[m + 3];
        a0 += X[i0 * F + f];
        a1 += X[i1 * F + f];
        a2 += X[i2 * F + f];
        a3 += X[i3 * F + f];
    }
    for (; m < t; ++m) a0 += X[g_adj_e[m] * F + f];
    g_Ae[e * F + f] = (a0 + a1 + a2 + a3) * g_Binv[e];
}

// Node aggregation + relu: out[v][f] = relu(Dinv[v] * sum_{e ∋ v} Ge[e][f])
template <int F>
__global__ void k_node_agg(float* __restrict__ out) {
    int v = blockIdx.x * (128 / F) + threadIdx.y;
    if (v >= N_V) return;
    int f = threadIdx.x;
    int s = g_off_v[v], t = g_off_v[v + 1];
    float a0 = 0.f, a1 = 0.f, a2 = 0.f, a3 = 0.f;
    int m = s;
    for (; m + 4 <= t; m += 4) {
        int i0 = g_adj_v[m + 0], i1 = g_adj_v[m + 1];
        int i2 = g_adj_v[m + 2], i3 = g_adj_v[m + 3];
        a0 += g_Ge[i0 * F + f];
        a1 += g_Ge[i1 * F + f];
        a2 += g_Ge[i2 * F + f];
        a3 += g_Ge[i3 * F + f];
    }
    for (; m < t; ++m) a0 += g_Ge[g_adj_v[m] * F + f];
    float r = (a0 + a1 + a2 + a3) * g_Dinv[v];
    out[v * F + f] = r > 0.f ? r : 0.f;
}

// ---------------------------------------------------------------------------
// Small fp32 GEMM: Ge[M x N] = Ae[M x K] @ W[K x N] + b, M = 10000.
// 32 rows per block, 4x4 register tile per thread, blockDim = 2N.
template <int K, int N>
__global__ void k_gemm(const float* __restrict__ W, const float* __restrict__ b) {
    constexpr int RB = 32;
    __shared__ float As[RB][33];
    __shared__ float Ws[32][N];
    const int tid = threadIdx.x;            // 2N threads
    const int tc = tid % (N / 4);
    const int tr = tid / (N / 4);           // 0..7
    const int row0 = blockIdx.x * RB;

    float acc[4][4];
#pragma unroll
    for (int i = 0; i < 4; i++)
#pragma unroll
        for (int j = 0; j < 4; j++) acc[i][j] = 0.f;

    for (int k0 = 0; k0 < K; k0 += 32) {
        for (int idx = tid; idx < RB * 32; idx += 2 * N) {
            int r = idx / 32, c = idx % 32;
            int gr = row0 + r;
            As[r][c] = (gr < N_E) ? g_Ae[gr * K + k0 + c] : 0.f;
        }
        for (int idx = tid; idx < 32 * N; idx += 2 * N) {
            int r = idx / N, c = idx % N;
            Ws[r][c] = W[(k0 + r) * N + c];
        }
        __syncthreads();
#pragma unroll
        for (int kk = 0; kk < 32; kk++) {
            float a[4];
#pragma unroll
            for (int i = 0; i < 4; i++) a[i] = As[tr * 4 + i][kk];
            float4 wv = *(const float4*)&Ws[kk][tc * 4];
            float w[4] = {wv.x, wv.y, wv.z, wv.w};
#pragma unroll
            for (int i = 0; i < 4; i++)
#pragma unroll
                for (int j = 0; j < 4; j++) acc[i][j] += a[i] * w[j];
        }
        __syncthreads();
    }
#pragma unroll
    for (int i = 0; i < 4; i++) {
        int gr = row0 + tr * 4 + i;
        if (gr < N_E) {
#pragma unroll
            for (int j = 0; j < 4; j++)
                g_Ge[gr * N + tc * 4 + j] = acc[i][j] + b[tc * 4 + j];
        }
    }
}

// ---------------------------------------------------------------------------
extern "C" void kernel_launch(void* const* d_in, const int* in_sizes, int n_in,
                              void* d_out, int out_size) {
    const float* x  = (const float*)d_in[0];
    const void*  ed = d_in[1];
    const float* w1 = (const float*)d_in[2];
    const float* b1 = (const float*)d_in[3];
    const float* w2 = (const float*)d_in[4];
    const float* b2 = (const float*)d_in[5];
    const float* w3 = (const float*)d_in[6];
    const float* b3 = (const float*)d_in[7];
    float* out = (float*)d_out;

    void *p_h1 = nullptr, *p_h2 = nullptr;
    cudaGetSymbolAddress(&p_h1, g_h1);
    cudaGetSymbolAddress(&p_h2, g_h2);
    float* h1 = (float*)p_h1;
    float* h2 = (float*)p_h2;

    // --- CSR build ---
    k_zero<<<128, 256>>>();
    k_detect<<<1, 256>>>((const unsigned int*)ed);
    k_hist<<<1024, 256>>>(ed);
    k_inv<<<(N_V + 255) / 256, 256>>>();
    k_scan<true><<<1, 1024>>>();
    k_scan<false><<<1, 1024>>>();
    k_scatter<<<1024, 256>>>(ed);

    const int GEMM_BLKS = (N_E + 31) / 32;   // 313

    // --- Layer 1: 128 -> 128 ---
    k_edge_agg<128><<<N_E, dim3(128, 1)>>>(x);
    k_gemm<128, 128><<<GEMM_BLKS, 256>>>(w1, b1);
    k_node_agg<128><<<N_V, dim3(128, 1)>>>(h1);

    // --- Layer 2: 128 -> 64 ---
    k_edge_agg<128><<<N_E, dim3(128, 1)>>>(h1);
    k_gemm<128, 64><<<GEMM_BLKS, 128>>>(w2, b2);
    k_node_agg<64><<<N_V / 2, dim3(64, 2)>>>(h2);

    // --- Layer 3: 64 -> 32 ---
    k_edge_agg<64><<<N_E / 2, dim3(64, 2)>>>(h2);
    k_gemm<64, 32><<<GEMM_BLKS, 64>>>(w3, b3);
    k_node_agg<32><<<N_V / 4, dim3(32, 4)>>>(out);
}

// round 2
// speedup vs baseline: 1.2603x; 1.2603x over previous
#include <cuda_runtime.h>
#include <cuda_fp16.h>

// ---------------------------------------------------------------------------
// HgnnEncoder: 3-layer hypergraph conv.
//   per layer:  Ae = B^-1 H^T X      (edge aggregation, fp16 gathers, fp32 acc)
//               Ge = Ae @ W + b      (GEMM on 10000 edge rows, fp16 output)
//               out = relu(D^-1 H Ge) (node aggregation, fp16 gathers)
// All gathered intermediates stored fp16 (halves L2 gather traffic);
// accumulation is fp32 throughout.
// ---------------------------------------------------------------------------

#define NNZ  800000
#define N_V  50000
#define N_E  10000

__device__ int    g_is64;
__device__ int    g_deg_e[N_E];
__device__ int    g_deg_v[N_V];
__device__ int    g_cur_e[N_E];
__device__ int    g_cur_v[N_V];
__device__ int    g_off_e[N_E + 1];
__device__ int    g_off_v[N_V + 1];
__device__ int    g_adj_e[NNZ];     // grouped by hyperedge, stores node ids
__device__ int    g_adj_v[NNZ];     // grouped by node, stores hyperedge ids
__device__ float  g_Binv[N_E];
__device__ float  g_Dinv[N_V];
__device__ float  g_Ae[N_E * 128];            // edge agg output (fp32, GEMM input)
__device__ __half g_Geh[N_E * 128];           // GEMM output (fp16, gathered)
__device__ __half g_Xh[(size_t)N_V * 128];    // fp16 copy of input X
__device__ __half g_h1[(size_t)N_V * 128];
__device__ __half g_h2[(size_t)N_V * 64];

// ---------------------------------------------------------------------------
// Zero counters + detect int64 vs int32 edge buffer.
// Values < 10000, so for int64 (LE) every odd 32-bit word of the head is 0.
__global__ void k_prep(const unsigned int* __restrict__ e32) {
    int stride = gridDim.x * blockDim.x;
    int i = blockIdx.x * blockDim.x + threadIdx.x;
    for (int j = i; j < N_E; j += stride) { g_deg_e[j] = 0; g_cur_e[j] = 0; }
    for (int j = i; j < N_V; j += stride) { g_deg_v[j] = 0; g_cur_v[j] = 0; }
    if (blockIdx.x == 0) {
        __shared__ int any;
        if (threadIdx.x == 0) any = 0;
        __syncthreads();
        unsigned int local = 0;
        for (int k = 1 + 2 * threadIdx.x; k < 8192; k += 2 * blockDim.x)
            local |= e32[k];
        if (local) any = 1;
        __syncthreads();
        if (threadIdx.x == 0) g_is64 = any ? 0 : 1;
    }
}

// Convert X (fp32) -> g_Xh (fp16), vectorized.
__global__ void k_convert(const float* __restrict__ x) {
    const int n = N_V * 64;  // half2 count
    const float2* x2 = (const float2*)x;
    __half2* o = (__half2*)g_Xh;
    int stride = gridDim.x * blockDim.x;
    for (int i = blockIdx.x * blockDim.x + threadIdx.x; i < n; i += stride)
        o[i] = __float22half2_rn(x2[i]);
}

__device__ __forceinline__ int load_idx(const void* edge, int i, int is64) {
    if (is64) return (int)((const long long*)edge)[i];
    return ((const int*)edge)[i];
}

__global__ void k_hist(const void* __restrict__ edge) {
    int is64 = g_is64;
    int stride = gridDim.x * blockDim.x;
    for (int i = blockIdx.x * blockDim.x + threadIdx.x; i < NNZ; i += stride) {
        int v = load_idx(edge, i, is64);
        int e = load_idx(edge, NNZ + i, is64);
        atomicAdd(&g_deg_v[v], 1);
        atomicAdd(&g_deg_e[e], 1);
    }
}

// Block-wide scan of deg -> exclusive offsets, plus reciprocal degree.
__device__ void scan_block(const int* __restrict__ deg, int* __restrict__ off,
                           float* __restrict__ inv, int n,
                           int* wsum, int* s_carry) {
    int tid = threadIdx.x, lane = tid & 31, wid = tid >> 5;
    if (tid == 0) { *s_carry = 0; off[0] = 0; }
    __syncthreads();
    for (int base = 0; base < n; base += 1024) {
        int i = base + tid;
        int d = (i < n) ? deg[i] : 0;
        if (i < n) inv[i] = d ? 1.0f / (float)d : 0.0f;
        int x = d;
#pragma unroll
        for (int s = 1; s < 32; s <<= 1) {
            int t = __shfl_up_sync(0xffffffffu, x, s);
            if (lane >= s) x += t;
        }
        if (lane == 31) wsum[wid] = x;
        __syncthreads();
        if (wid == 0) {
            int y = wsum[lane];
#pragma unroll
            for (int s = 1; s < 32; s <<= 1) {
                int t = __shfl_up_sync(0xffffffffu, y, s);
                if (lane >= s) y += t;
            }
            wsum[lane] = y;
        }
        __syncthreads();
        int warpoff = wid ? wsum[wid - 1] : 0;
        int carry = *s_carry;
        if (i < n) off[i + 1] = x + warpoff + carry;
        __syncthreads();
        if (tid == 0) *s_carry = carry + wsum[31];
        __syncthreads();
    }
}

__global__ void k_scaninv() {
    __shared__ int wsum[32];
    __shared__ int carry;
    scan_block(g_deg_e, g_off_e, g_Binv, N_E, wsum, &carry);
    __syncthreads();
    scan_block(g_deg_v, g_off_v, g_Dinv, N_V, wsum, &carry);
}

__global__ void k_scatter(const void* __restrict__ edge) {
    int is64 = g_is64;
    int stride = gridDim.x * blockDim.x;
    for (int i = blockIdx.x * blockDim.x + threadIdx.x; i < NNZ; i += stride) {
        int v = load_idx(edge, i, is64);
        int e = load_idx(edge, NNZ + i, is64);
        int pe = atomicAdd(&g_cur_e[e], 1);
        g_adj_e[g_off_e[e] + pe] = v;
        int pv = atomicAdd(&g_cur_v[v], 1);
        g_adj_v[g_off_v[v] + pv] = e;
    }
}

// ---------------------------------------------------------------------------
// Edge aggregation: Ae[e][:] = Binv[e] * sum_{v in e} Xh[v][:]
// blockDim.x = F/2 threads per row (each owns one half2), blockDim.y rows/block.
template <int F>
__global__ void k_edge_agg(const __half* __restrict__ X) {
    int e = blockIdx.x * blockDim.y + threadIdx.y;
    if (e >= N_E) return;
    int f2 = threadIdx.x;
    const __half2* Xh = (const __half2*)X;
    int s = g_off_e[e], t = g_off_e[e + 1];
    float a0x = 0.f, a0y = 0.f, a1x = 0.f, a1y = 0.f;
    float a2x = 0.f, a2y = 0.f, a3x = 0.f, a3y = 0.f;
    int m = s;
    for (; m + 4 <= t; m += 4) {
        int i0 = g_adj_e[m + 0], i1 = g_adj_e[m + 1];
        int i2 = g_adj_e[m + 2], i3 = g_adj_e[m + 3];
        float2 v0 = __half22float2(Xh[i0 * (F / 2) + f2]);
        float2 v1 = __half22float2(Xh[i1 * (F / 2) + f2]);
        float2 v2 = __half22float2(Xh[i2 * (F / 2) + f2]);
        float2 v3 = __half22float2(Xh[i3 * (F / 2) + f2]);
        a0x += v0.x; a0y += v0.y; a1x += v1.x; a1y += v1.y;
        a2x += v2.x; a2y += v2.y; a3x += v3.x; a3y += v3.y;
    }
    for (; m < t; ++m) {
        float2 v = __half22float2(Xh[g_adj_e[m] * (F / 2) + f2]);
        a0x += v.x; a0y += v.y;
    }
    float b = g_Binv[e];
    float2 r;
    r.x = (a0x + a1x + a2x + a3x) * b;
    r.y = (a0y + a1y + a2y + a3y) * b;
    ((float2*)g_Ae)[e * (F / 2) + f2] = r;
}

// Node aggregation + relu: out[v][:] = relu(Dinv[v] * sum_{e ∋ v} Ge[e][:])
// FINAL=true writes fp32 (d_out, zero-fills inactive rows);
// FINAL=false writes fp16 and skips inactive rows (never gathered).
template <int F, bool FINAL>
__global__ void k_node_agg(void* __restrict__ outp) {
    int v = blockIdx.x * blockDim.y + threadIdx.y;
    if (v >= N_V) return;
    int f2 = threadIdx.x;
    int s = g_off_v[v], t = g_off_v[v + 1];
    if (s == t) {
        if (FINAL) ((float2*)outp)[v * (F / 2) + f2] = make_float2(0.f, 0.f);
        return;
    }
    const __half2* G = (const __half2*)g_Geh;
    float a0x = 0.f, a0y = 0.f, a1x = 0.f, a1y = 0.f;
    float a2x = 0.f, a2y = 0.f, a3x = 0.f, a3y = 0.f;
    int m = s;
    for (; m + 4 <= t; m += 4) {
        int i0 = g_adj_v[m + 0], i1 = g_adj_v[m + 1];
        int i2 = g_adj_v[m + 2], i3 = g_adj_v[m + 3];
        float2 v0 = __half22float2(G[i0 * (F / 2) + f2]);
        float2 v1 = __half22float2(G[i1 * (F / 2) + f2]);
        float2 v2 = __half22float2(G[i2 * (F / 2) + f2]);
        float2 v3 = __half22float2(G[i3 * (F / 2) + f2]);
        a0x += v0.x; a0y += v0.y; a1x += v1.x; a1y += v1.y;
        a2x += v2.x; a2y += v2.y; a3x += v3.x; a3y += v3.y;
    }
    for (; m < t; ++m) {
        float2 v = __half22float2(G[g_adj_v[m] * (F / 2) + f2]);
        a0x += v.x; a0y += v.y;
    }
    float d = g_Dinv[v];
    float rx = fmaxf((a0x + a1x + a2x + a3x) * d, 0.f);
    float ry = fmaxf((a0y + a1y + a2y + a3y) * d, 0.f);
    if (FINAL) {
        ((float2*)outp)[v * (F / 2) + f2] = make_float2(rx, ry);
    } else {
        ((__half2*)outp)[v * (F / 2) + f2] = __floats2half2_rn(rx, ry);
    }
}

// ---------------------------------------------------------------------------
// Small fp32 GEMM: Geh[M x N] = half(Ae[M x K] @ W[K x N] + b), M = 10000.
// 32 rows per block, 4x4 register tile per thread, blockDim = 2N.
template <int K, int N>
__global__ void k_gemm(const float* __restrict__ W, const float* __restrict__ b) {
    constexpr int RB = 32;
    __shared__ float As[RB][33];
    __shared__ float Ws[32][N];
    const int tid = threadIdx.x;            // 2N threads
    const int tc = tid % (N / 4);
    const int tr = tid / (N / 4);           // 0..7
    const int row0 = blockIdx.x * RB;

    float acc[4][4];
#pragma unroll
    for (int i = 0; i < 4; i++)
#pragma unroll
        for (int j = 0; j < 4; j++) acc[i][j] = 0.f;

    for (int k0 = 0; k0 < K; k0 += 32) {
        for (int idx = tid; idx < RB * 32; idx += 2 * N) {
            int r = idx / 32, c = idx % 32;
            int gr = row0 + r;
            As[r][c] = (gr < N_E) ? g_Ae[gr * K + k0 + c] : 0.f;
        }
        for (int idx = tid; idx < 32 * N; idx += 2 * N) {
            int r = idx / N, c = idx % N;
            Ws[r][c] = W[(k0 + r) * N + c];
        }
        __syncthreads();
#pragma unroll
        for (int kk = 0; kk < 32; kk++) {
            float a[4];
#pragma unroll
            for (int i = 0; i < 4; i++) a[i] = As[tr * 4 + i][kk];
            float4 wv = *(const float4*)&Ws[kk][tc * 4];
            float w[4] = {wv.x, wv.y, wv.z, wv.w};
#pragma unroll
            for (int i = 0; i < 4; i++)
#pragma unroll
                for (int j = 0; j < 4; j++) acc[i][j] += a[i] * w[j];
        }
        __syncthreads();
    }
    float b0 = b[tc * 4 + 0], b1 = b[tc * 4 + 1];
    float b2 = b[tc * 4 + 2], b3 = b[tc * 4 + 3];
#pragma unroll
    for (int i = 0; i < 4; i++) {
        int gr = row0 + tr * 4 + i;
        if (gr < N_E) {
            __half2 h0 = __floats2half2_rn(acc[i][0] + b0, acc[i][1] + b1);
            __half2 h1 = __floats2half2_rn(acc[i][2] + b2, acc[i][3] + b3);
            __half2* dst = (__half2*)&g_Geh[gr * N + tc * 4];
            dst[0] = h0;
            dst[1] = h1;
        }
    }
}

// ---------------------------------------------------------------------------
extern "C" void kernel_launch(void* const* d_in, const int* in_sizes, int n_in,
                              void* d_out, int out_size) {
    const float* x  = (const float*)d_in[0];
    const void*  ed = d_in[1];
    const float* w1 = (const float*)d_in[2];
    const float* b1 = (const float*)d_in[3];
    const float* w2 = (const float*)d_in[4];
    const float* b2 = (const float*)d_in[5];
    const float* w3 = (const float*)d_in[6];
    const float* b3 = (const float*)d_in[7];

    void *p_xh = nullptr, *p_h1 = nullptr, *p_h2 = nullptr;
    cudaGetSymbolAddress(&p_xh, g_Xh);
    cudaGetSymbolAddress(&p_h1, g_h1);
    cudaGetSymbolAddress(&p_h2, g_h2);
    const __half* xh = (const __half*)p_xh;
    __half* h1 = (__half*)p_h1;
    __half* h2 = (__half*)p_h2;

    // --- CSR build + fp16 conversion (launches 1-5) ---
    k_prep<<<128, 256>>>((const unsigned int*)ed);
    k_convert<<<512, 256>>>(x);
    k_hist<<<1024, 256>>>(ed);
    k_scaninv<<<1, 1024>>>();
    k_scatter<<<1024, 256>>>(ed);

    const int GEMM_BLKS = (N_E + 31) / 32;   // 313

    // --- Layer 1: 128 -> 128 ---   (launch 6 = edge_agg<128>, ncu target)
    k_edge_agg<128><<<N_E / 4, dim3(64, 4)>>>(xh);
    k_gemm<128, 128><<<GEMM_BLKS, 256>>>(w1, b1);
    k_node_agg<128, false><<<N_V / 4, dim3(64, 4)>>>(h1);

    // --- Layer 2: 128 -> 64 ---
    k_edge_agg<128><<<N_E / 4, dim3(64, 4)>>>(h1);
    k_gemm<128, 64><<<GEMM_BLKS, 128>>>(w2, b2);
    k_node_agg<64, false><<<N_V / 8, dim3(32, 8)>>>(h2);

    // --- Layer 3: 64 -> 32 ---
    k_edge_agg<64><<<N_E / 8, dim3(32, 8)>>>(h2);
    k_gemm<64, 32><<<GEMM_BLKS, 64>>>(w3, b3);
    k_node_agg<32, true><<<N_V / 16, dim3(16, 16)>>>(d_out);
}

// round 3
// speedup vs baseline: 1.4363x; 1.1396x over previous
#include <cuda_runtime.h>
#include <cuda_fp16.h>

// ---------------------------------------------------------------------------
// HgnnEncoder: 3-layer hypergraph conv.
//   per layer:  Ae = B^-1 H^T X      (edge aggregation, fp16 gathers, fp32 acc)
//               Ge = Ae @ W + b      (GEMM on 10000 edge rows, fp16 output)
//               out = relu(D^-1 H Ge) (node aggregation, fp16 gathers)
// CSR built per launch with a fully parallel 3-phase scan (no single-block
// serialization). All gathered intermediates fp16; accumulation fp32.
// ---------------------------------------------------------------------------

#define NNZ  800000
#define N_V  50000
#define N_E  10000

#define SBLK_E 10                    // ceil(N_E / 1024)
#define SBLK_V 49                    // ceil(N_V / 1024)
#define SBLK   (SBLK_E + SBLK_V)     // 59

__device__ int    g_is64;
__device__ int    g_deg_e[N_E];
__device__ int    g_deg_v[N_V];
__device__ int    g_cur_e[N_E];
__device__ int    g_cur_v[N_V];
__device__ int    g_off_e[N_E + 1];
__device__ int    g_off_v[N_V + 1];
__device__ int    g_bsum[SBLK];
__device__ int    g_bpref[SBLK];
__device__ int    g_adj_e[NNZ];     // grouped by hyperedge, stores node ids
__device__ int    g_adj_v[NNZ];     // grouped by node, stores hyperedge ids
__device__ float  g_Binv[N_E];
__device__ float  g_Dinv[N_V];
__device__ __align__(16) float  g_Ae[N_E * 128];          // edge agg out (fp32)
__device__ __align__(16) __half g_Geh[N_E * 128];         // GEMM out (fp16)
__device__ __align__(16) __half g_Xh[(size_t)N_V * 128];  // fp16 copy of X
__device__ __align__(16) __half g_h1[(size_t)N_V * 128];
__device__ __align__(16) __half g_h2[(size_t)N_V * 64];

// ---------------------------------------------------------------------------
// Zero counters + detect int64 vs int32 edge buffer.
// Values < 10000, so for int64 (LE) every odd 32-bit word of the head is 0.
__global__ void k_prep(const unsigned int* __restrict__ e32) {
    int stride = gridDim.x * blockDim.x;
    int i = blockIdx.x * blockDim.x + threadIdx.x;
    for (int j = i; j < N_E; j += stride) { g_deg_e[j] = 0; g_cur_e[j] = 0; }
    for (int j = i; j < N_V; j += stride) { g_deg_v[j] = 0; g_cur_v[j] = 0; }
    if (blockIdx.x == 0) {
        __shared__ int any;
        if (threadIdx.x == 0) any = 0;
        __syncthreads();
        unsigned int local = 0;
        for (int k = 1 + 2 * threadIdx.x; k < 8192; k += 2 * blockDim.x)
            local |= e32[k];
        if (local) any = 1;
        __syncthreads();
        if (threadIdx.x == 0) g_is64 = any ? 0 : 1;
    }
}

// Convert X (fp32) -> g_Xh (fp16), vectorized.
__global__ void k_convert(const float* __restrict__ x) {
    const int n = N_V * 64;  // half2 count
    const float2* x2 = (const float2*)x;
    __half2* o = (__half2*)g_Xh;
    int stride = gridDim.x * blockDim.x;
    for (int i = blockIdx.x * blockDim.x + threadIdx.x; i < n; i += stride)
        o[i] = __float22half2_rn(x2[i]);
}

// Load index i of a logical int array that may be int64 (LE): read only the
// low 32-bit word.
__device__ __forceinline__ int load_idx(const int* __restrict__ e32, int i, int sh) {
    return e32[i << sh];
}

__global__ void k_hist(const int* __restrict__ e32) {
    int sh = g_is64;   // 1 if int64 (stride 2 words), 0 if int32
    int stride = gridDim.x * blockDim.x;
    for (int i = blockIdx.x * blockDim.x + threadIdx.x; i < NNZ; i += stride) {
        int v = load_idx(e32, i, sh);
        int e = load_idx(e32, NNZ + i, sh);
        atomicAdd(&g_deg_v[v], 1);
        atomicAdd(&g_deg_e[e], 1);
    }
}

// --- 3-phase parallel scan over (deg_e ++ deg_v) -------------------------
// Blocks 0..SBLK_E-1 cover deg_e, blocks SBLK_E..SBLK-1 cover deg_v.
__device__ __forceinline__ void seg_of_block(int b, const int*& deg, int& base, int& n) {
    if (b < SBLK_E) { deg = g_deg_e; base = b * 1024;            n = N_E; }
    else            { deg = g_deg_v; base = (b - SBLK_E) * 1024; n = N_V; }
}

__global__ void k_bsum() {
    __shared__ int wsum[32];
    const int* deg; int base, n;
    seg_of_block(blockIdx.x, deg, base, n);
    int i = base + threadIdx.x;
    int x = (i < n) ? deg[i] : 0;
#pragma unroll
    for (int s = 16; s; s >>= 1) x += __shfl_down_sync(0xffffffffu, x, s);
    int lane = threadIdx.x & 31, wid = threadIdx.x >> 5;
    if (lane == 0) wsum[wid] = x;
    __syncthreads();
    if (wid == 0) {
        int y = wsum[lane];
#pragma unroll
        for (int s = 16; s; s >>= 1) y += __shfl_down_sync(0xffffffffu, y, s);
        if (lane == 0) g_bsum[blockIdx.x] = y;
    }
}

__global__ void k_bscan() {
    if (threadIdx.x == 0) {
        int c = 0;
        for (int b = 0; b < SBLK_E; b++) { g_bpref[b] = c; c += g_bsum[b]; }
        c = 0;
        for (int b = SBLK_E; b < SBLK; b++) { g_bpref[b] = c; c += g_bsum[b]; }
    }
}

__global__ void k_bwrite() {
    __shared__ int wsum[32];
    const int* deg; int base, n;
    seg_of_block(blockIdx.x, deg, base, n);
    int* off   = (blockIdx.x < SBLK_E) ? g_off_e : g_off_v;
    float* inv = (blockIdx.x < SBLK_E) ? g_Binv  : g_Dinv;
    int tid = threadIdx.x, lane = tid & 31, wid = tid >> 5;
    int i = base + tid;
    int d = (i < n) ? deg[i] : 0;
    if (i < n) inv[i] = d ? 1.0f / (float)d : 0.0f;
    int x = d;
#pragma unroll
    for (int s = 1; s < 32; s <<= 1) {
        int t = __shfl_up_sync(0xffffffffu, x, s);
        if (lane >= s) x += t;
    }
    if (lane == 31) wsum[wid] = x;
    __syncthreads();
    if (wid == 0) {
        int y = wsum[lane];
#pragma unroll
        for (int s = 1; s < 32; s <<= 1) {
            int t = __shfl_up_sync(0xffffffffu, y, s);
            if (lane >= s) y += t;
        }
        wsum[lane] = y;
    }
    __syncthreads();
    int incl = x + (wid ? wsum[wid - 1] : 0) + g_bpref[blockIdx.x];
    if (i < n) off[i + 1] = incl;
    if (tid == 0 && base == 0) off[0] = 0;
}

__global__ void k_scatter(const int* __restrict__ e32) {
    int sh = g_is64;
    int stride = gridDim.x * blockDim.x;
    for (int i = blockIdx.x * blockDim.x + threadIdx.x; i < NNZ; i += stride) {
        int v = load_idx(e32, i, sh);
        int e = load_idx(e32, NNZ + i, sh);
        int pe = atomicAdd(&g_cur_e[e], 1);
        g_adj_e[g_off_e[e] + pe] = v;
        int pv = atomicAdd(&g_cur_v[v], 1);
        g_adj_v[g_off_v[v] + pv] = e;
    }
}

// ---------------------------------------------------------------------------
// Edge aggregation: Ae[e][:] = Binv[e] * sum_{v in e} Xh[v][:]
// blockDim.x = F/2 threads per row (each owns one half2), blockDim.y rows/block.
template <int F>
__global__ void k_edge_agg(const __half* __restrict__ X) {
    int e = blockIdx.x * blockDim.y + threadIdx.y;
    if (e >= N_E) return;
    int f2 = threadIdx.x;
    const __half2* Xh = (const __half2*)X;
    int s = g_off_e[e], t = g_off_e[e + 1];
    float a0x = 0.f, a0y = 0.f, a1x = 0.f, a1y = 0.f;
    float a2x = 0.f, a2y = 0.f, a3x = 0.f, a3y = 0.f;
    int m = s;
    for (; m + 4 <= t; m += 4) {
        int i0 = g_adj_e[m + 0], i1 = g_adj_e[m + 1];
        int i2 = g_adj_e[m + 2], i3 = g_adj_e[m + 3];
        float2 v0 = __half22float2(Xh[i0 * (F / 2) + f2]);
        float2 v1 = __half22float2(Xh[i1 * (F / 2) + f2]);
        float2 v2 = __half22float2(Xh[i2 * (F / 2) + f2]);
        float2 v3 = __half22float2(Xh[i3 * (F / 2) + f2]);
        a0x += v0.x; a0y += v0.y; a1x += v1.x; a1y += v1.y;
        a2x += v2.x; a2y += v2.y; a3x += v3.x; a3y += v3.y;
    }
    for (; m < t; ++m) {
        float2 v = __half22float2(Xh[g_adj_e[m] * (F / 2) + f2]);
        a0x += v.x; a0y += v.y;
    }
    float b = g_Binv[e];
    float2 r;
    r.x = (a0x + a1x + a2x + a3x) * b;
    r.y = (a0y + a1y + a2y + a3y) * b;
    ((float2*)g_Ae)[e * (F / 2) + f2] = r;
}

// Node aggregation + relu: out[v][:] = relu(Dinv[v] * sum_{e ∋ v} Ge[e][:])
// FINAL=true writes fp32 (d_out, zero-fills inactive rows);
// FINAL=false writes fp16 and skips inactive rows (never gathered).
template <int F, bool FINAL>
__global__ void k_node_agg(void* __restrict__ outp) {
    int v = blockIdx.x * blockDim.y + threadIdx.y;
    if (v >= N_V) return;
    int f2 = threadIdx.x;
    int s = g_off_v[v], t = g_off_v[v + 1];
    if (s == t) {
        if (FINAL) ((float2*)outp)[v * (F / 2) + f2] = make_float2(0.f, 0.f);
        return;
    }
    const __half2* G = (const __half2*)g_Geh;
    float a0x = 0.f, a0y = 0.f, a1x = 0.f, a1y = 0.f;
    float a2x = 0.f, a2y = 0.f, a3x = 0.f, a3y = 0.f;
    int m = s;
    for (; m + 4 <= t; m += 4) {
        int i0 = g_adj_v[m + 0], i1 = g_adj_v[m + 1];
        int i2 = g_adj_v[m + 2], i3 = g_adj_v[m + 3];
        float2 v0 = __half22float2(G[i0 * (F / 2) + f2]);
        float2 v1 = __half22float2(G[i1 * (F / 2) + f2]);
        float2 v2 = __half22float2(G[i2 * (F / 2) + f2]);
        float2 v3 = __half22float2(G[i3 * (F / 2) + f2]);
        a0x += v0.x; a0y += v0.y; a1x += v1.x; a1y += v1.y;
        a2x += v2.x; a2y += v2.y; a3x += v3.x; a3y += v3.y;
    }
    for (; m < t; ++m) {
        float2 v = __half22float2(G[g_adj_v[m] * (F / 2) + f2]);
        a0x += v.x; a0y += v.y;
    }
    float d = g_Dinv[v];
    float rx = fmaxf((a0x + a1x + a2x + a3x) * d, 0.f);
    float ry = fmaxf((a0y + a1y + a2y + a3y) * d, 0.f);
    if (FINAL) {
        ((float2*)outp)[v * (F / 2) + f2] = make_float2(rx, ry);
    } else {
        ((__half2*)outp)[v * (F / 2) + f2] = __floats2half2_rn(rx, ry);
    }
}

// ---------------------------------------------------------------------------
// Small fp32 GEMM: Geh[M x N] = half(Ae[M x K] @ W[K x N] + b), M = 10000.
// 32 rows per block, 4x4 register tile per thread, blockDim = 2N.
template <int K, int N>
__global__ void k_gemm(const float* __restrict__ W, const float* __restrict__ b) {
    constexpr int RB = 32;
    __shared__ float As[RB][33];
    __shared__ float Ws[32][N];
    const int tid = threadIdx.x;            // 2N threads
    const int tc = tid % (N / 4);
    const int tr = tid / (N / 4);           // 0..7
    const int row0 = blockIdx.x * RB;

    float acc[4][4];
#pragma unroll
    for (int i = 0; i < 4; i++)
#pragma unroll
        for (int j = 0; j < 4; j++) acc[i][j] = 0.f;

    for (int k0 = 0; k0 < K; k0 += 32) {
        for (int idx = tid; idx < RB * 32; idx += 2 * N) {
            int r = idx / 32, c = idx % 32;
            int gr = row0 + r;
            As[r][c] = (gr < N_E) ? g_Ae[gr * K + k0 + c] : 0.f;
        }
        for (int idx = tid; idx < 32 * N; idx += 2 * N) {
            int r = idx / N, c = idx % N;
            Ws[r][c] = W[(k0 + r) * N + c];
        }
        __syncthreads();
#pragma unroll
        for (int kk = 0; kk < 32; kk++) {
            float a[4];
#pragma unroll
            for (int i = 0; i < 4; i++) a[i] = As[tr * 4 + i][kk];
            float4 wv = *(const float4*)&Ws[kk][tc * 4];
            float w[4] = {wv.x, wv.y, wv.z, wv.w};
#pragma unroll
            for (int i = 0; i < 4; i++)
#pragma unroll
                for (int j = 0; j < 4; j++) acc[i][j] += a[i] * w[j];
        }
        __syncthreads();
    }
    float b0 = b[tc * 4 + 0], b1 = b[tc * 4 + 1];
    float b2 = b[tc * 4 + 2], b3 = b[tc * 4 + 3];
#pragma unroll
    for (int i = 0; i < 4; i++) {
        int gr = row0 + tr * 4 + i;
        if (gr < N_E) {
            __half2 h0 = __floats2half2_rn(acc[i][0] + b0, acc[i][1] + b1);
            __half2 h1 = __floats2half2_rn(acc[i][2] + b2, acc[i][3] + b3);
            __half2* dst = (__half2*)&g_Geh[gr * N + tc * 4];
            dst[0] = h0;
            dst[1] = h1;
        }
    }
}

// ---------------------------------------------------------------------------
extern "C" void kernel_launch(void* const* d_in, const int* in_sizes, int n_in,
                              void* d_out, int out_size) {
    const float* x  = (const float*)d_in[0];
    const void*  ed = d_in[1];
    const float* w1 = (const float*)d_in[2];
    const float* b1 = (const float*)d_in[3];
    const float* w2 = (const float*)d_in[4];
    const float* b2 = (const float*)d_in[5];
    const float* w3 = (const float*)d_in[6];
    const float* b3 = (const float*)d_in[7];

    void *p_xh = nullptr, *p_h1 = nullptr, *p_h2 = nullptr;
    cudaGetSymbolAddress(&p_xh, g_Xh);
    cudaGetSymbolAddress(&p_h1, g_h1);
    cudaGetSymbolAddress(&p_h2, g_h2);
    const __half* xh = (const __half*)p_xh;
    __half* h1 = (__half*)p_h1;
    __half* h2 = (__half*)p_h2;

    // --- CSR build + fp16 conversion ---
    k_prep<<<128, 256>>>((const unsigned int*)ed);
    k_convert<<<512, 256>>>(x);
    k_hist<<<1024, 256>>>((const int*)ed);
    k_bsum<<<SBLK, 1024>>>();
    k_bscan<<<1, 32>>>();
    k_bwrite<<<SBLK, 1024>>>();
    k_scatter<<<1024, 256>>>((const int*)ed);

    const int GEMM_BLKS = (N_E + 31) / 32;   // 313

    // --- Layer 1: 128 -> 128 ---
    k_edge_agg<128><<<N_E / 4, dim3(64, 4)>>>(xh);
    k_gemm<128, 128><<<GEMM_BLKS, 256>>>(w1, b1);
    k_node_agg<128, false><<<N_V / 4, dim3(64, 4)>>>(h1);

    // --- Layer 2: 128 -> 64 ---
    k_edge_agg<128><<<N_E / 4, dim3(64, 4)>>>(h1);
    k_gemm<128, 64><<<GEMM_BLKS, 128>>>(w2, b2);
    k_node_agg<64, false><<<N_V / 8, dim3(32, 8)>>>(h2);

    // --- Layer 3: 64 -> 32 ---
    k_edge_agg<64><<<N_E / 8, dim3(32, 8)>>>(h2);
    k_gemm<64, 32><<<GEMM_BLKS, 64>>>(w3, b3);
    k_node_agg<32, true><<<N_V / 16, dim3(16, 16)>>>(d_out);
}

// round 4
// speedup vs baseline: 1.6741x; 1.1655x over previous
#include <cuda_runtime.h>
#include <cuda_fp16.h>

// ---------------------------------------------------------------------------
// HgnnEncoder: 3-layer hypergraph conv.
//   per layer:  Ae = B^-1 H^T X      (edge aggregation, fp16 gathers, fp32 acc)
//               Ge = Ae @ W + b      (GEMM on 10000 edge rows, fp16 output)
//               out = relu(D^-1 H Ge) (node aggregation, fp16 gathers)
// CSR build: hist -> single-kernel decoupled-lookback scan -> scatter.
// Gathers use 8B (uint2 = 4 half) loads; accumulation fp32 throughout.
// ---------------------------------------------------------------------------

#define NNZ  800000
#define N_V  50000
#define N_E  10000

#define SBLK_E 10                    // ceil(N_E / 1024)
#define SBLK_V 49                    // ceil(N_V / 1024)
#define SBLK   (SBLK_E + SBLK_V)     // 59

__device__ int    g_is64;
__device__ int    g_deg_e[N_E];
__device__ int    g_deg_v[N_V];
__device__ int    g_cur_e[N_E];
__device__ int    g_cur_v[N_V];
__device__ int    g_off_e[N_E + 1];
__device__ int    g_off_v[N_V + 1];
__device__ int    g_bsum[SBLK];
__device__ int    g_bflag[SBLK];
__device__ int    g_adj_e[NNZ];     // grouped by hyperedge, stores node ids
__device__ int    g_adj_v[NNZ];     // grouped by node, stores hyperedge ids
__device__ float  g_Binv[N_E];
__device__ float  g_Dinv[N_V];
__device__ __align__(16) float  g_Ae[N_E * 128];          // edge agg out (fp32)
__device__ __align__(16) __half g_Geh[N_E * 128];         // GEMM out (fp16)
__device__ __align__(16) __half g_Xh[(size_t)N_V * 128];  // fp16 copy of X
__device__ __align__(16) __half g_h1[(size_t)N_V * 128];
__device__ __align__(16) __half g_h2[(size_t)N_V * 64];

// ---------------------------------------------------------------------------
// Zero counters/flags + detect int64 vs int32 edge buffer.
// Values < 10000, so for int64 (LE) every odd 32-bit word of the head is 0.
__global__ void k_prep(const unsigned int* __restrict__ e32) {
    int stride = gridDim.x * blockDim.x;
    int i = blockIdx.x * blockDim.x + threadIdx.x;
    for (int j = i; j < N_E; j += stride) { g_deg_e[j] = 0; g_cur_e[j] = 0; }
    for (int j = i; j < N_V; j += stride) { g_deg_v[j] = 0; g_cur_v[j] = 0; }
    if (i < SBLK) g_bflag[i] = 0;
    if (blockIdx.x == 0) {
        __shared__ int any;
        if (threadIdx.x == 0) any = 0;
        __syncthreads();
        unsigned int local = 0;
        for (int k = 1 + 2 * threadIdx.x; k < 8192; k += 2 * blockDim.x)
            local |= e32[k];
        if (local) any = 1;
        __syncthreads();
        if (threadIdx.x == 0) g_is64 = any ? 0 : 1;
    }
}

// Convert X (fp32) -> g_Xh (fp16), vectorized.
__global__ void k_convert(const float* __restrict__ x) {
    const int n = N_V * 32;  // float4 -> half2x2 count
    const float4* x4 = (const float4*)x;
    uint2* o = (uint2*)g_Xh;
    int stride = gridDim.x * blockDim.x;
    for (int i = blockIdx.x * blockDim.x + threadIdx.x; i < n; i += stride) {
        float4 v = x4[i];
        __half2 h0 = __floats2half2_rn(v.x, v.y);
        __half2 h1 = __floats2half2_rn(v.z, v.w);
        uint2 w;
        w.x = *(unsigned int*)&h0;
        w.y = *(unsigned int*)&h1;
        o[i] = w;
    }
}

// Load index i of a logical int array that may be int64 (LE): read only the
// low 32-bit word.
__device__ __forceinline__ int load_idx(const int* __restrict__ e32, int i, int sh) {
    return e32[i << sh];
}

__global__ void k_hist(const int* __restrict__ e32) {
    int sh = g_is64;   // 1 if int64 (stride 2 words), 0 if int32
    int stride = gridDim.x * blockDim.x;
    for (int i = blockIdx.x * blockDim.x + threadIdx.x; i < NNZ; i += stride) {
        int v = load_idx(e32, i, sh);
        int e = load_idx(e32, NNZ + i, sh);
        atomicAdd(&g_deg_v[v], 1);
        atomicAdd(&g_deg_e[e], 1);
    }
}

// --- Single-kernel decoupled-lookback scan over (deg_e ++ deg_v) ----------
// Blocks 0..SBLK_E-1 cover deg_e, blocks SBLK_E..SBLK-1 cover deg_v.
// All 59 blocks are wave-1 resident; block b spins only on lower-indexed
// blocks of its own segment (<=48 predecessors, parallel spin).
__global__ void k_scan() {
    __shared__ int wsum[32];
    __shared__ int predsum[SBLK_V];
    __shared__ int s_pref;

    int b = blockIdx.x;
    bool isE = (b < SBLK_E);
    const int* __restrict__ deg = isE ? g_deg_e : g_deg_v;
    int* __restrict__ off = isE ? g_off_e : g_off_v;
    float* __restrict__ inv = isE ? g_Binv : g_Dinv;
    int segFirst = isE ? 0 : SBLK_E;
    int bl = b - segFirst;
    int n = isE ? N_E : N_V;
    int base = bl * 1024;

    int tid = threadIdx.x, lane = tid & 31, wid = tid >> 5;
    int i = base + tid;
    int d = (i < n) ? deg[i] : 0;
    if (i < n) inv[i] = d ? 1.0f / (float)d : 0.0f;

    // Block-local inclusive scan.
    int x = d;
#pragma unroll
    for (int s = 1; s < 32; s <<= 1) {
        int t = __shfl_up_sync(0xffffffffu, x, s);
        if (lane >= s) x += t;
    }
    if (lane == 31) wsum[wid] = x;
    __syncthreads();
    if (wid == 0) {
        int y = wsum[lane];
#pragma unroll
        for (int s = 1; s < 32; s <<= 1) {
            int t = __shfl_up_sync(0xffffffffu, y, s);
            if (lane >= s) y += t;
        }
        wsum[lane] = y;
    }
    __syncthreads();
    int incl = x + (wid ? wsum[wid - 1] : 0);

    // Publish block aggregate.
    if (tid == 0) {
        g_bsum[b] = wsum[31];
        __threadfence();
        atomicExch(&g_bflag[b], 1);
    }

    // Lookback: threads 0..bl-1 each spin on one predecessor.
    if (tid < bl) {
        while (atomicAdd(&g_bflag[segFirst + tid], 0) == 0) {}
        predsum[tid] = atomicAdd(&g_bsum[segFirst + tid], 0);
    }
    __syncthreads();
    if (tid == 0) {
        int c = 0;
        for (int k = 0; k < bl; k++) c += predsum[k];
        s_pref = c;
    }
    __syncthreads();

    if (i < n) off[i + 1] = incl + s_pref;
    if (tid == 0 && bl == 0) off[0] = 0;
}

__global__ void k_scatter(const int* __restrict__ e32) {
    int sh = g_is64;
    int stride = gridDim.x * blockDim.x;
    for (int i = blockIdx.x * blockDim.x + threadIdx.x; i < NNZ; i += stride) {
        int v = load_idx(e32, i, sh);
        int e = load_idx(e32, NNZ + i, sh);
        int pe = atomicAdd(&g_cur_e[e], 1);
        g_adj_e[g_off_e[e] + pe] = v;
        int pv = atomicAdd(&g_cur_v[v], 1);
        g_adj_v[g_off_v[v] + pv] = e;
    }
}

// ---------------------------------------------------------------------------
// Edge aggregation: Ae[e][:] = Binv[e] * sum_{v in e} Xh[v][:]
// Each thread owns 4 halves (one uint2); F/4 threads per row.
template <int F>
__global__ void k_edge_agg(const __half* __restrict__ X) {
    int e = blockIdx.x * blockDim.y + threadIdx.y;
    if (e >= N_E) return;
    const int RPR = F / 4;               // uint2 per row
    int f = threadIdx.x;
    const uint2* __restrict__ Xv = (const uint2*)X;
    int s = g_off_e[e], t = g_off_e[e + 1];
    float acc[4][4];
#pragma unroll
    for (int u = 0; u < 4; u++)
#pragma unroll
        for (int j = 0; j < 4; j++) acc[u][j] = 0.f;
    int m = s;
    for (; m + 4 <= t; m += 4) {
#pragma unroll
        for (int u = 0; u < 4; u++) {
            int idx = g_adj_e[m + u];
            uint2 w = Xv[idx * RPR + f];
            float2 p = __half22float2(*(__half2*)&w.x);
            float2 q = __half22float2(*(__half2*)&w.y);
            acc[u][0] += p.x; acc[u][1] += p.y;
            acc[u][2] += q.x; acc[u][3] += q.y;
        }
    }
    for (; m < t; ++m) {
        int idx = g_adj_e[m];
        uint2 w = Xv[idx * RPR + f];
        float2 p = __half22float2(*(__half2*)&w.x);
        float2 q = __half22float2(*(__half2*)&w.y);
        acc[0][0] += p.x; acc[0][1] += p.y;
        acc[0][2] += q.x; acc[0][3] += q.y;
    }
    float bv = g_Binv[e];
    float4 r;
    r.x = (acc[0][0] + acc[1][0] + acc[2][0] + acc[3][0]) * bv;
    r.y = (acc[0][1] + acc[1][1] + acc[2][1] + acc[3][1]) * bv;
    r.z = (acc[0][2] + acc[1][2] + acc[2][2] + acc[3][2]) * bv;
    r.w = (acc[0][3] + acc[1][3] + acc[2][3] + acc[3][3]) * bv;
    ((float4*)g_Ae)[e * RPR + f] = r;
}

// Node aggregation + relu: out[v][:] = relu(Dinv[v] * sum_{e ∋ v} Ge[e][:])
// FINAL=true writes fp32 (d_out, zero-fills inactive rows);
// FINAL=false writes fp16 and skips inactive rows (never gathered).
template <int F, bool FINAL>
__global__ void k_node_agg(void* __restrict__ outp) {
    int v = blockIdx.x * blockDim.y + threadIdx.y;
    if (v >= N_V) return;
    const int RPR = F / 4;
    int f = threadIdx.x;
    int s = g_off_v[v], t = g_off_v[v + 1];
    if (s == t) {
        if (FINAL)
            ((float4*)outp)[v * RPR + f] = make_float4(0.f, 0.f, 0.f, 0.f);
        return;
    }
    const uint2* __restrict__ G = (const uint2*)g_Geh;
    float acc[4][4];
#pragma unroll
    for (int u = 0; u < 4; u++)
#pragma unroll
        for (int j = 0; j < 4; j++) acc[u][j] = 0.f;
    int m = s;
    for (; m + 4 <= t; m += 4) {
#pragma unroll
        for (int u = 0; u < 4; u++) {
            int idx = g_adj_v[m + u];
            uint2 w = G[idx * RPR + f];
            float2 p = __half22float2(*(__half2*)&w.x);
            float2 q = __half22float2(*(__half2*)&w.y);
            acc[u][0] += p.x; acc[u][1] += p.y;
            acc[u][2] += q.x; acc[u][3] += q.y;
        }
    }
    for (; m < t; ++m) {
        int idx = g_adj_v[m];
        uint2 w = G[idx * RPR + f];
        float2 p = __half22float2(*(__half2*)&w.x);
        float2 q = __half22float2(*(__half2*)&w.y);
        acc[0][0] += p.x; acc[0][1] += p.y;
        acc[0][2] += q.x; acc[0][3] += q.y;
    }
    float dv = g_Dinv[v];
    float r0 = fmaxf((acc[0][0] + acc[1][0] + acc[2][0] + acc[3][0]) * dv, 0.f);
    float r1 = fmaxf((acc[0][1] + acc[1][1] + acc[2][1] + acc[3][1]) * dv, 0.f);
    float r2 = fmaxf((acc[0][2] + acc[1][2] + acc[2][2] + acc[3][2]) * dv, 0.f);
    float r3 = fmaxf((acc[0][3] + acc[1][3] + acc[2][3] + acc[3][3]) * dv, 0.f);
    if (FINAL) {
        ((float4*)outp)[v * RPR + f] = make_float4(r0, r1, r2, r3);
    } else {
        __half2 h0 = __floats2half2_rn(r0, r1);
        __half2 h1 = __floats2half2_rn(r2, r3);
        uint2 w;
        w.x = *(unsigned int*)&h0;
        w.y = *(unsigned int*)&h1;
        ((uint2*)outp)[v * RPR + f] = w;
    }
}

// ---------------------------------------------------------------------------
// Small fp32 GEMM: Geh[M x N] = half(Ae[M x K] @ W[K x N] + b), M = 10000.
// 32 rows per block, 4x4 register tile per thread, blockDim = 2N.
template <int K, int N>
__global__ void k_gemm(const float* __restrict__ W, const float* __restrict__ b) {
    constexpr int RB = 32;
    __shared__ float As[RB][33];
    __shared__ float Ws[32][N];
    const int tid = threadIdx.x;            // 2N threads
    const int tc = tid % (N / 4);
    const int tr = tid / (N / 4);           // 0..7
    const int row0 = blockIdx.x * RB;

    float acc[4][4];
#pragma unroll
    for (int i = 0; i < 4; i++)
#pragma unroll
        for (int j = 0; j < 4; j++) acc[i][j] = 0.f;

    for (int k0 = 0; k0 < K; k0 += 32) {
        for (int idx = tid; idx < RB * 32; idx += 2 * N) {
            int r = idx / 32, c = idx % 32;
            int gr = row0 + r;
            As[r][c] = (gr < N_E) ? g_Ae[gr * K + k0 + c] : 0.f;
        }
        for (int idx = tid; idx < 32 * N; idx += 2 * N) {
            int r = idx / N, c = idx % N;
            Ws[r][c] = W[(k0 + r) * N + c];
        }
        __syncthreads();
#pragma unroll
        for (int kk = 0; kk < 32; kk++) {
            float a[4];
#pragma unroll
            for (int i = 0; i < 4; i++) a[i] = As[tr * 4 + i][kk];
            float4 wv = *(const float4*)&Ws[kk][tc * 4];
            float w[4] = {wv.x, wv.y, wv.z, wv.w};
#pragma unroll
            for (int i = 0; i < 4; i++)
#pragma unroll
                for (int j = 0; j < 4; j++) acc[i][j] += a[i] * w[j];
        }
        __syncthreads();
    }
    float b0 = b[tc * 4 + 0], b1 = b[tc * 4 + 1];
    float b2 = b[tc * 4 + 2], b3 = b[tc * 4 + 3];
#pragma unroll
    for (int i = 0; i < 4; i++) {
        int gr = row0 + tr * 4 + i;
        if (gr < N_E) {
            __half2 h0 = __floats2half2_rn(acc[i][0] + b0, acc[i][1] + b1);
            __half2 h1 = __floats2half2_rn(acc[i][2] + b2, acc[i][3] + b3);
            __half2* dst = (__half2*)&g_Geh[gr * N + tc * 4];
            dst[0] = h0;
            dst[1] = h1;
        }
    }
}

// ---------------------------------------------------------------------------
extern "C" void kernel_launch(void* const* d_in, const int* in_sizes, int n_in,
                              void* d_out, int out_size) {
    const float* x  = (const float*)d_in[0];
    const void*  ed = d_in[1];
    const float* w1 = (const float*)d_in[2];
    const float* b1 = (const float*)d_in[3];
    const float* w2 = (const float*)d_in[4];
    const float* b2 = (const float*)d_in[5];
    const float* w3 = (const float*)d_in[6];
    const float* b3 = (const float*)d_in[7];

    void *p_xh = nullptr, *p_h1 = nullptr, *p_h2 = nullptr;
    cudaGetSymbolAddress(&p_xh, g_Xh);
    cudaGetSymbolAddress(&p_h1, g_h1);
    cudaGetSymbolAddress(&p_h2, g_h2);
    const __half* xh = (const __half*)p_xh;
    __half* h1 = (__half*)p_h1;
    __half* h2 = (__half*)p_h2;

    // --- CSR build + fp16 conversion (launches 1-5) ---
    k_prep<<<128, 256>>>((const unsigned int*)ed);
    k_convert<<<512, 256>>>(x);
    k_hist<<<1024, 256>>>((const int*)ed);
    k_scan<<<SBLK, 1024>>>();
    k_scatter<<<1024, 256>>>((const int*)ed);

    const int GEMM_BLKS = (N_E + 31) / 32;   // 313

    // --- Layer 1: 128 -> 128 ---   (launch 6 = edge_agg<128>, ncu target)
    k_edge_agg<128><<<N_E / 8, dim3(32, 8)>>>(xh);
    k_gemm<128, 128><<<GEMM_BLKS, 256>>>(w1, b1);
    k_node_agg<128, false><<<N_V / 8, dim3(32, 8)>>>(h1);

    // --- Layer 2: 128 -> 64 ---
    k_edge_agg<128><<<N_E / 8, dim3(32, 8)>>>(h1);
    k_gemm<128, 64><<<GEMM_BLKS, 128>>>(w2, b2);
    k_node_agg<64, false><<<N_V / 16, dim3(16, 16)>>>(h2);

    // --- Layer 3: 64 -> 32 ---
    k_edge_agg<64><<<N_E / 16, dim3(16, 16)>>>(h2);
    k_gemm<64, 32><<<GEMM_BLKS, 64>>>(w3, b3);
    k_node_agg<32, true><<<(N_V + 31) / 32, dim3(8, 32)>>>(d_out);
}

// round 5
// speedup vs baseline: 1.7551x; 1.0484x over previous
#include <cuda_runtime.h>
#include <cuda_fp16.h>

// ---------------------------------------------------------------------------
// HgnnEncoder: 3-layer hypergraph conv, reordered as
//   per layer:  Y  = X W + b          (GEMM on ACTIVE nodes only, F_out)
//               Ae = B^-1 H^T Y       (edge aggregation at F_out, fp16)
//               out= relu(D^-1 H Ae)  (node aggregation at F_out)
// Valid since B^-1 H^T (XW + 1b^T) = (B^-1 H^T X)W + b on non-empty edges,
// and empty-edge rows are never gathered back.
// CSR + active-node list built per launch (hist -> lookback scan -> scatter).
// ---------------------------------------------------------------------------

#define NNZ  800000
#define N_V  50000
#define N_E  10000

#define SBLK_E 10                    // ceil(N_E / 1024)
#define SBLK_V 49                    // ceil(N_V / 1024)
#define SBLK   (SBLK_E + SBLK_V)     // 59

__device__ int    g_is64;
__device__ int    g_deg_e[N_E];
__device__ int    g_deg_v[N_V];
__device__ int    g_cur_e[N_E];
__device__ int    g_cur_v[N_V];
__device__ int    g_off_e[N_E + 1];
__device__ int    g_off_v[N_V + 1];
__device__ int    g_bsum[SBLK];
__device__ int    g_bsum2[SBLK];
__device__ int    g_bflag[SBLK];
__device__ int    g_act[N_V];        // compacted active node ids
__device__ int    g_nact;
__device__ int    g_adj_e[NNZ];      // grouped by hyperedge, stores node ids
__device__ int    g_adj_v[NNZ];      // grouped by node, stores hyperedge ids
__device__ float  g_Binv[N_E];
__device__ float  g_Dinv[N_V];
__device__ __align__(16) __half g_Y[(size_t)N_V * 128];   // node GEMM output
__device__ __align__(16) __half g_AeH[N_E * 128];         // edge agg output
__device__ __align__(16) __half g_h1[(size_t)N_V * 128];
__device__ __align__(16) __half g_h2[(size_t)N_V * 64];

// ---------------------------------------------------------------------------
// Zero counters/flags + detect int64 vs int32 edge buffer.
// Values < 10000, so for int64 (LE) every odd 32-bit word of the head is 0.
__global__ void k_prep(const unsigned int* __restrict__ e32) {
    int stride = gridDim.x * blockDim.x;
    int i = blockIdx.x * blockDim.x + threadIdx.x;
    for (int j = i; j < N_E; j += stride) { g_deg_e[j] = 0; g_cur_e[j] = 0; }
    for (int j = i; j < N_V; j += stride) { g_deg_v[j] = 0; g_cur_v[j] = 0; }
    if (i < SBLK) g_bflag[i] = 0;
    if (blockIdx.x == 0) {
        __shared__ int any;
        if (threadIdx.x == 0) any = 0;
        __syncthreads();
        unsigned int local = 0;
        for (int k = 1 + 2 * threadIdx.x; k < 8192; k += 2 * blockDim.x)
            local |= e32[k];
        if (local) any = 1;
        __syncthreads();
        if (threadIdx.x == 0) g_is64 = any ? 0 : 1;
    }
}

// Load 4 consecutive logical indices starting at i (i % 4 == 0).
// For int64 (LE) data, read two int4 and keep the low words.
__device__ __forceinline__ int4 load_idx4(const int* __restrict__ e32, int i, int sh) {
    if (sh) {
        int4 a = ((const int4*)e32)[i >> 1];
        int4 b = ((const int4*)e32)[(i >> 1) + 1];
        return make_int4(a.x, a.z, b.x, b.z);
    }
    return ((const int4*)e32)[i >> 2];
}

__global__ void k_hist(const int* __restrict__ e32) {
    int sh = g_is64;
    int stride = gridDim.x * blockDim.x * 4;
    for (int i = (blockIdx.x * blockDim.x + threadIdx.x) * 4; i < NNZ; i += stride) {
        int4 v = load_idx4(e32, i, sh);
        int4 e = load_idx4(e32, NNZ + i, sh);
        atomicAdd(&g_deg_v[v.x], 1); atomicAdd(&g_deg_v[v.y], 1);
        atomicAdd(&g_deg_v[v.z], 1); atomicAdd(&g_deg_v[v.w], 1);
        atomicAdd(&g_deg_e[e.x], 1); atomicAdd(&g_deg_e[e.y], 1);
        atomicAdd(&g_deg_e[e.z], 1); atomicAdd(&g_deg_e[e.w], 1);
    }
}

// --- Single-kernel decoupled-lookback dual scan over (deg_e ++ deg_v) ------
// Scans degree (-> CSR offsets) and active indicator (-> compact node list).
__global__ void k_scan() {
    __shared__ int wsum[32], wsum2[32];
    __shared__ int predsum[SBLK_V], predsum2[SBLK_V];
    __shared__ int s_pref, s_pref2;

    int b = blockIdx.x;
    bool isE = (b < SBLK_E);
    const int* __restrict__ deg = isE ? g_deg_e : g_deg_v;
    int* __restrict__ off = isE ? g_off_e : g_off_v;
    float* __restrict__ inv = isE ? g_Binv : g_Dinv;
    int segFirst = isE ? 0 : SBLK_E;
    int bl = b - segFirst;
    int n = isE ? N_E : N_V;
    int base = bl * 1024;

    int tid = threadIdx.x, lane = tid & 31, wid = tid >> 5;
    int i = base + tid;
    int d = (i < n) ? deg[i] : 0;
    if (i < n) inv[i] = d ? 1.0f / (float)d : 0.0f;

    int x = d;
    int y = (d > 0) ? 1 : 0;
#pragma unroll
    for (int s = 1; s < 32; s <<= 1) {
        int tx = __shfl_up_sync(0xffffffffu, x, s);
        int ty = __shfl_up_sync(0xffffffffu, y, s);
        if (lane >= s) { x += tx; y += ty; }
    }
    if (lane == 31) { wsum[wid] = x; wsum2[wid] = y; }
    __syncthreads();
    if (wid == 0) {
        int a = wsum[lane], c = wsum2[lane];
#pragma unroll
        for (int s = 1; s < 32; s <<= 1) {
            int ta = __shfl_up_sync(0xffffffffu, a, s);
            int tc = __shfl_up_sync(0xffffffffu, c, s);
            if (lane >= s) { a += ta; c += tc; }
        }
        wsum[lane] = a; wsum2[lane] = c;
    }
    __syncthreads();
    int incl = x + (wid ? wsum[wid - 1] : 0);
    int incl2 = y + (wid ? wsum2[wid - 1] : 0);

    if (tid == 0) {
        g_bsum[b] = wsum[31];
        g_bsum2[b] = wsum2[31];
        __threadfence();
        atomicExch(&g_bflag[b], 1);
    }

    if (tid < bl) {
        while (atomicAdd(&g_bflag[segFirst + tid], 0) == 0) {}
        predsum[tid] = atomicAdd(&g_bsum[segFirst + tid], 0);
        predsum2[tid] = atomicAdd(&g_bsum2[segFirst + tid], 0);
    }
    __syncthreads();
    if (tid == 0) {
        int c = 0, c2 = 0;
        for (int k = 0; k < bl; k++) { c += predsum[k]; c2 += predsum2[k]; }
        s_pref = c; s_pref2 = c2;
    }
    __syncthreads();

    if (i < n) off[i + 1] = incl + s_pref;
    if (tid == 0 && bl == 0) off[0] = 0;

    if (!isE) {
        if (i < n && d > 0) g_act[incl2 - 1 + s_pref2] = i;
        if (i == n - 1) g_nact = incl2 + s_pref2;
    }
}

__global__ void k_scatter(const int* __restrict__ e32) {
    int sh = g_is64;
    int stride = gridDim.x * blockDim.x * 4;
    for (int i = (blockIdx.x * blockDim.x + threadIdx.x) * 4; i < NNZ; i += stride) {
        int4 v = load_idx4(e32, i, sh);
        int4 e = load_idx4(e32, NNZ + i, sh);
#pragma unroll
        for (int u = 0; u < 4; u++) {
            int vv = (u == 0) ? v.x : (u == 1) ? v.y : (u == 2) ? v.z : v.w;
            int ee = (u == 0) ? e.x : (u == 1) ? e.y : (u == 2) ? e.z : e.w;
            int pe = atomicAdd(&g_cur_e[ee], 1);
            g_adj_e[g_off_e[ee] + pe] = vv;
            int pv = atomicAdd(&g_cur_v[vv], 1);
            g_adj_v[g_off_v[vv] + pv] = ee;
        }
    }
}

// ---------------------------------------------------------------------------
// Node GEMM over the ACTIVE list: Y[act[s]] = X[act[s]] @ W + b  (fp16 out).
// Grid-stride over 32-row slabs; XT = float (layer 1) or __half (layers 2,3).
template <int K, int N, typename XT>
__global__ void k_gemm(const XT* __restrict__ X,
                       const float* __restrict__ W,
                       const float* __restrict__ b) {
    __shared__ float As[32][33];
    __shared__ float Ws[32][N];
    __shared__ int sAct[32];
    const int tid = threadIdx.x;            // 2N threads
    const int tc = tid % (N / 4);
    const int tr = tid / (N / 4);            // 0..7
    const int nact = g_nact;

    for (int s0 = blockIdx.x * 32; s0 < nact; s0 += gridDim.x * 32) {
        if (tid < 32)
            sAct[tid] = (s0 + tid < nact) ? g_act[s0 + tid] : -1;
        __syncthreads();

        float acc[4][4];
#pragma unroll
        for (int i = 0; i < 4; i++)
#pragma unroll
            for (int j = 0; j < 4; j++) acc[i][j] = 0.f;

        for (int k0 = 0; k0 < K; k0 += 32) {
            // load 32 rows x 32 k of X (gathered via act ids), 4 elems/thread
            for (int idx = tid; idx < 32 * 8; idx += 2 * N) {
                int r = idx / 8, c = idx % 8;
                int row = sAct[r];
                float4 vv;
                if (row < 0) {
                    vv = make_float4(0.f, 0.f, 0.f, 0.f);
                } else if (sizeof(XT) == 4) {
                    vv = ((const float4*)X)[row * (K / 4) + k0 / 4 + c];
                } else {
                    uint2 w = ((const uint2*)X)[row * (K / 4) + k0 / 4 + c];
                    float2 p = __half22float2(*(__half2*)&w.x);
                    float2 q = __half22float2(*(__half2*)&w.y);
                    vv = make_float4(p.x, p.y, q.x, q.y);
                }
                As[r][c * 4 + 0] = vv.x; As[r][c * 4 + 1] = vv.y;
                As[r][c * 4 + 2] = vv.z; As[r][c * 4 + 3] = vv.w;
            }
            for (int idx = tid; idx < 32 * N; idx += 2 * N) {
                int r = idx / N, c = idx % N;
                Ws[r][c] = W[(k0 + r) * N + c];
            }
            __syncthreads();
#pragma unroll
            for (int kk = 0; kk < 32; kk++) {
                float a[4];
#pragma unroll
                for (int i = 0; i < 4; i++) a[i] = As[tr * 4 + i][kk];
                float4 wv = *(const float4*)&Ws[kk][tc * 4];
#pragma unroll
                for (int i = 0; i < 4; i++) {
                    acc[i][0] += a[i] * wv.x;
                    acc[i][1] += a[i] * wv.y;
                    acc[i][2] += a[i] * wv.z;
                    acc[i][3] += a[i] * wv.w;
                }
            }
            __syncthreads();
        }
        float b0 = b[tc * 4 + 0], b1 = b[tc * 4 + 1];
        float b2 = b[tc * 4 + 2], b3 = b[tc * 4 + 3];
#pragma unroll
        for (int i = 0; i < 4; i++) {
            int row = sAct[tr * 4 + i];
            if (row >= 0) {
                __half2 h0 = __floats2half2_rn(acc[i][0] + b0, acc[i][1] + b1);
                __half2 h1 = __floats2half2_rn(acc[i][2] + b2, acc[i][3] + b3);
                __half2* dst = (__half2*)&g_Y[(size_t)row * N + tc * 4];
                dst[0] = h0;
                dst[1] = h1;
            }
        }
        __syncthreads();
    }
}

// ---------------------------------------------------------------------------
// Edge aggregation at F_out: AeH[e][:] = Binv[e] * sum_{v in e} Y[v][:]
// Each thread owns 4 halves (one uint2); F/4 threads per row.
template <int F>
__global__ void k_edge_agg() {
    int e = blockIdx.x * blockDim.y + threadIdx.y;
    if (e >= N_E) return;
    const int RPR = F / 4;               // uint2 per row
    int f = threadIdx.x;
    const uint2* __restrict__ Yv = (const uint2*)g_Y;
    int s = g_off_e[e], t = g_off_e[e + 1];
    float acc[4][4];
#pragma unroll
    for (int u = 0; u < 4; u++)
#pragma unroll
        for (int j = 0; j < 4; j++) acc[u][j] = 0.f;
    int m = s;
    for (; m + 4 <= t; m += 4) {
#pragma unroll
        for (int u = 0; u < 4; u++) {
            int idx = g_adj_e[m + u];
            uint2 w = Yv[idx * RPR + f];
            float2 p = __half22float2(*(__half2*)&w.x);
            float2 q = __half22float2(*(__half2*)&w.y);
            acc[u][0] += p.x; acc[u][1] += p.y;
            acc[u][2] += q.x; acc[u][3] += q.y;
        }
    }
    for (; m < t; ++m) {
        int idx = g_adj_e[m];
        uint2 w = Yv[idx * RPR + f];
        float2 p = __half22float2(*(__half2*)&w.x);
        float2 q = __half22float2(*(__half2*)&w.y);
        acc[0][0] += p.x; acc[0][1] += p.y;
        acc[0][2] += q.x; acc[0][3] += q.y;
    }
    float bv = g_Binv[e];
    __half2 h0 = __floats2half2_rn((acc[0][0] + acc[1][0] + acc[2][0] + acc[3][0]) * bv,
                                   (acc[0][1] + acc[1][1] + acc[2][1] + acc[3][1]) * bv);
    __half2 h1 = __floats2half2_rn((acc[0][2] + acc[1][2] + acc[2][2] + acc[3][2]) * bv,
                                   (acc[0][3] + acc[1][3] + acc[2][3] + acc[3][3]) * bv);
    uint2 w;
    w.x = *(unsigned int*)&h0;
    w.y = *(unsigned int*)&h1;
    ((uint2*)g_AeH)[e * RPR + f] = w;
}

// Node aggregation + relu: out[v][:] = relu(Dinv[v] * sum_{e ∋ v} AeH[e][:])
// FINAL=true writes fp32 (d_out, zero-fills inactive rows);
// FINAL=false writes fp16 and skips inactive rows (never gathered).
template <int F, bool FINAL>
__global__ void k_node_agg(void* __restrict__ outp) {
    int v = blockIdx.x * blockDim.y + threadIdx.y;
    if (v >= N_V) return;
    const int RPR = F / 4;
    int f = threadIdx.x;
    int s = g_off_v[v], t = g_off_v[v + 1];
    if (s == t) {
        if (FINAL)
            ((float4*)outp)[v * RPR + f] = make_float4(0.f, 0.f, 0.f, 0.f);
        return;
    }
    const uint2* __restrict__ G = (const uint2*)g_AeH;
    float acc[4][4];
#pragma unroll
    for (int u = 0; u < 4; u++)
#pragma unroll
        for (int j = 0; j < 4; j++) acc[u][j] = 0.f;
    int m = s;
    for (; m + 4 <= t; m += 4) {
#pragma unroll
        for (int u = 0; u < 4; u++) {
            int idx = g_adj_v[m + u];
            uint2 w = G[idx * RPR + f];
            float2 p = __half22float2(*(__half2*)&w.x);
            float2 q = __half22float2(*(__half2*)&w.y);
            acc[u][0] += p.x; acc[u][1] += p.y;
            acc[u][2] += q.x; acc[u][3] += q.y;
        }
    }
    for (; m < t; ++m) {
        int idx = g_adj_v[m];
        uint2 w = G[idx * RPR + f];
        float2 p = __half22float2(*(__half2*)&w.x);
        float2 q = __half22float2(*(__half2*)&w.y);
        acc[0][0] += p.x; acc[0][1] += p.y;
        acc[0][2] += q.x; acc[0][3] += q.y;
    }
    float dv = g_Dinv[v];
    float r0 = fmaxf((acc[0][0] + acc[1][0] + acc[2][0] + acc[3][0]) * dv, 0.f);
    float r1 = fmaxf((acc[0][1] + acc[1][1] + acc[2][1] + acc[3][1]) * dv, 0.f);
    float r2 = fmaxf((acc[0][2] + acc[1][2] + acc[2][2] + acc[3][2]) * dv, 0.f);
    float r3 = fmaxf((acc[0][3] + acc[1][3] + acc[2][3] + acc[3][3]) * dv, 0.f);
    if (FINAL) {
        ((float4*)outp)[v * RPR + f] = make_float4(r0, r1, r2, r3);
    } else {
        __half2 h0 = __floats2half2_rn(r0, r1);
        __half2 h1 = __floats2half2_rn(r2, r3);
        uint2 w;
        w.x = *(unsigned int*)&h0;
        w.y = *(unsigned int*)&h1;
        ((uint2*)outp)[v * RPR + f] = w;
    }
}

// ---------------------------------------------------------------------------
extern "C" void kernel_launch(void* const* d_in, const int* in_sizes, int n_in,
                              void* d_out, int out_size) {
    const float* x  = (const float*)d_in[0];
    const void*  ed = d_in[1];
    const float* w1 = (const float*)d_in[2];
    const float* b1 = (const float*)d_in[3];
    const float* w2 = (const float*)d_in[4];
    const float* b2 = (const float*)d_in[5];
    const float* w3 = (const float*)d_in[6];
    const float* b3 = (const float*)d_in[7];

    void *p_h1 = nullptr, *p_h2 = nullptr;
    cudaGetSymbolAddress(&p_h1, g_h1);
    cudaGetSymbolAddress(&p_h2, g_h2);
    const __half* h1 = (const __half*)p_h1;
    const __half* h2 = (const __half*)p_h2;

    // --- CSR + active-list build ---
    k_prep<<<128, 256>>>((const unsigned int*)ed);
    k_hist<<<782, 256>>>((const int*)ed);
    k_scan<<<SBLK, 1024>>>();
    k_scatter<<<782, 256>>>((const int*)ed);

    const int GEMM_BLKS = 313;   // covers 10016 rows per sweep; loops if more

    // --- Layer 1: 128 -> 128 ---
    k_gemm<128, 128, float><<<GEMM_BLKS, 256>>>(x, w1, b1);
    k_edge_agg<128><<<N_E / 8, dim3(32, 8)>>>();
    k_node_agg<128, false><<<N_V / 8, dim3(32, 8)>>>((void*)h1);

    // --- Layer 2: 128 -> 64 ---
    k_gemm<128, 64, __half><<<GEMM_BLKS, 128>>>(h1, w2, b2);
    k_edge_agg<64><<<N_E / 16, dim3(16, 16)>>>();
    k_node_agg<64, false><<<N_V / 16, dim3(16, 16)>>>((void*)h2);

    // --- Layer 3: 64 -> 32 ---
    k_gemm<64, 32, __half><<<GEMM_BLKS, 64>>>(h2, w3, b3);
    k_edge_agg<32><<<(N_E + 31) / 32, dim3(8, 32)>>>();
    k_node_agg<32, true><<<(N_V + 31) / 32, dim3(8, 32)>>>(d_out);
}

// round 6
// speedup vs baseline: 1.8546x; 1.0567x over previous
#include <cuda_runtime.h>
#include <cuda_fp16.h>

// ---------------------------------------------------------------------------
// HgnnEncoder: 3-layer hypergraph conv, reordered as
//   per layer:  Y  = X W + b          (GEMM on ACTIVE nodes only, F_out)
//               Ae = B^-1 H^T Y       (edge aggregation at F_out, fp16)
//               out= relu(D^-1 H Ae)  (node aggregation at F_out)
// CSR + active list built per launch:
//   hist (atomics, returns = ranks) -> lookback scan -> atomic-FREE scatter.
// ---------------------------------------------------------------------------

#define NNZ  800000
#define N_V  50000
#define N_E  10000

#define SBLK_E 10                    // ceil(N_E / 1024)
#define SBLK_V 49                    // ceil(N_V / 1024)
#define SBLK   (SBLK_E + SBLK_V)     // 59

__device__ int    g_is64;
__device__ int    g_deg_e[N_E];
__device__ int    g_deg_v[N_V];
__device__ int    g_off_e[N_E + 1];
__device__ int    g_off_v[N_V + 1];
__device__ int    g_bsum[SBLK];
__device__ int    g_bsum2[SBLK];
__device__ int    g_bflag[SBLK];
__device__ int    g_act[N_V];        // compacted active node ids
__device__ int    g_nact;
__device__ __align__(16) int g_rank_e[NNZ];  // rank of incidence within its edge
__device__ __align__(16) int g_rank_v[NNZ];  // rank of incidence within its node
__device__ int    g_adj_e[NNZ];      // grouped by hyperedge, stores node ids
__device__ int    g_adj_v[NNZ];      // grouped by node, stores hyperedge ids
__device__ float  g_Binv[N_E];
__device__ float  g_Dinv[N_V];
__device__ __align__(16) __half g_Y[(size_t)N_V * 128];   // node GEMM output
__device__ __align__(16) __half g_AeH[N_E * 128];         // edge agg output
__device__ __align__(16) __half g_h1[(size_t)N_V * 128];
__device__ __align__(16) __half g_h2[(size_t)N_V * 64];

// ---------------------------------------------------------------------------
// Zero counters/flags + detect int64 vs int32 edge buffer.
// Values < 10000, so for int64 (LE) every odd 32-bit word of the head is 0.
__global__ void k_prep(const unsigned int* __restrict__ e32) {
    int stride = gridDim.x * blockDim.x;
    int i = blockIdx.x * blockDim.x + threadIdx.x;
    for (int j = i; j < N_E; j += stride) g_deg_e[j] = 0;
    for (int j = i; j < N_V; j += stride) g_deg_v[j] = 0;
    if (i < SBLK) g_bflag[i] = 0;
    if (blockIdx.x == 0) {
        __shared__ int any;
        if (threadIdx.x == 0) any = 0;
        __syncthreads();
        unsigned int local = 0;
        for (int k = 1 + 2 * threadIdx.x; k < 8192; k += 2 * blockDim.x)
            local |= e32[k];
        if (local) any = 1;
        __syncthreads();
        if (threadIdx.x == 0) g_is64 = any ? 0 : 1;
    }
}

// Load 4 consecutive logical indices starting at i (i % 4 == 0).
// For int64 (LE) data, read two int4 and keep the low words.
__device__ __forceinline__ int4 load_idx4(const int* __restrict__ e32, int i, int sh) {
    if (sh) {
        int4 a = ((const int4*)e32)[i >> 1];
        int4 b = ((const int4*)e32)[(i >> 1) + 1];
        return make_int4(a.x, a.z, b.x, b.z);
    }
    return ((const int4*)e32)[i >> 2];
}

// Histogram; atomic returns are the per-key ranks, saved for the scatter pass.
__global__ void k_hist(const int* __restrict__ e32) {
    int sh = g_is64;
    int stride = gridDim.x * blockDim.x * 4;
    for (int i = (blockIdx.x * blockDim.x + threadIdx.x) * 4; i < NNZ; i += stride) {
        int4 v = load_idx4(e32, i, sh);
        int4 e = load_idx4(e32, NNZ + i, sh);
        int4 rv, re;
        rv.x = atomicAdd(&g_deg_v[v.x], 1);
        rv.y = atomicAdd(&g_deg_v[v.y], 1);
        rv.z = atomicAdd(&g_deg_v[v.z], 1);
        rv.w = atomicAdd(&g_deg_v[v.w], 1);
        re.x = atomicAdd(&g_deg_e[e.x], 1);
        re.y = atomicAdd(&g_deg_e[e.y], 1);
        re.z = atomicAdd(&g_deg_e[e.z], 1);
        re.w = atomicAdd(&g_deg_e[e.w], 1);
        ((int4*)g_rank_v)[i >> 2] = rv;
        ((int4*)g_rank_e)[i >> 2] = re;
    }
}

// --- Single-kernel decoupled-lookback dual scan over (deg_e ++ deg_v) ------
// Scans degree (-> CSR offsets) and active indicator (-> compact node list).
__global__ void k_scan() {
    __shared__ int wsum[32], wsum2[32];
    __shared__ int predsum[SBLK_V], predsum2[SBLK_V];
    __shared__ int s_pref, s_pref2;

    int b = blockIdx.x;
    bool isE = (b < SBLK_E);
    const int* __restrict__ deg = isE ? g_deg_e : g_deg_v;
    int* __restrict__ off = isE ? g_off_e : g_off_v;
    float* __restrict__ inv = isE ? g_Binv : g_Dinv;
    int segFirst = isE ? 0 : SBLK_E;
    int bl = b - segFirst;
    int n = isE ? N_E : N_V;
    int base = bl * 1024;

    int tid = threadIdx.x, lane = tid & 31, wid = tid >> 5;
    int i = base + tid;
    int d = (i < n) ? deg[i] : 0;
    if (i < n) inv[i] = d ? 1.0f / (float)d : 0.0f;

    int x = d;
    int y = (d > 0) ? 1 : 0;
#pragma unroll
    for (int s = 1; s < 32; s <<= 1) {
        int tx = __shfl_up_sync(0xffffffffu, x, s);
        int ty = __shfl_up_sync(0xffffffffu, y, s);
        if (lane >= s) { x += tx; y += ty; }
    }
    if (lane == 31) { wsum[wid] = x; wsum2[wid] = y; }
    __syncthreads();
    if (wid == 0) {
        int a = wsum[lane], c = wsum2[lane];
#pragma unroll
        for (int s = 1; s < 32; s <<= 1) {
            int ta = __shfl_up_sync(0xffffffffu, a, s);
            int tc = __shfl_up_sync(0xffffffffu, c, s);
            if (lane >= s) { a += ta; c += tc; }
        }
        wsum[lane] = a; wsum2[lane] = c;
    }
    __syncthreads();
    int incl = x + (wid ? wsum[wid - 1] : 0);
    int incl2 = y + (wid ? wsum2[wid - 1] : 0);

    if (tid == 0) {
        g_bsum[b] = wsum[31];
        g_bsum2[b] = wsum2[31];
        __threadfence();
        atomicExch(&g_bflag[b], 1);
    }

    if (tid < bl) {
        while (atomicAdd(&g_bflag[segFirst + tid], 0) == 0) {}
        predsum[tid] = atomicAdd(&g_bsum[segFirst + tid], 0);
        predsum2[tid] = atomicAdd(&g_bsum2[segFirst + tid], 0);
    }
    __syncthreads();
    if (tid == 0) {
        int c = 0, c2 = 0;
        for (int k = 0; k < bl; k++) { c += predsum[k]; c2 += predsum2[k]; }
        s_pref = c; s_pref2 = c2;
    }
    __syncthreads();

    if (i < n) off[i + 1] = incl + s_pref;
    if (tid == 0 && bl == 0) off[0] = 0;

    if (!isE) {
        if (i < n && d > 0) g_act[incl2 - 1 + s_pref2] = i;
        if (i == n - 1) g_nact = incl2 + s_pref2;
    }
}

// Atomic-free scatter: position = offset[key] + precomputed rank.
__global__ void k_scatter(const int* __restrict__ e32) {
    int sh = g_is64;
    int stride = gridDim.x * blockDim.x * 4;
    for (int i = (blockIdx.x * blockDim.x + threadIdx.x) * 4; i < NNZ; i += stride) {
        int4 v = load_idx4(e32, i, sh);
        int4 e = load_idx4(e32, NNZ + i, sh);
        int4 rv = ((const int4*)g_rank_v)[i >> 2];
        int4 re = ((const int4*)g_rank_e)[i >> 2];
        g_adj_e[g_off_e[e.x] + re.x] = v.x;
        g_adj_e[g_off_e[e.y] + re.y] = v.y;
        g_adj_e[g_off_e[e.z] + re.z] = v.z;
        g_adj_e[g_off_e[e.w] + re.w] = v.w;
        g_adj_v[g_off_v[v.x] + rv.x] = e.x;
        g_adj_v[g_off_v[v.y] + rv.y] = e.y;
        g_adj_v[g_off_v[v.z] + rv.z] = e.z;
        g_adj_v[g_off_v[v.w] + rv.w] = e.w;
    }
}

// ---------------------------------------------------------------------------
// Node GEMM over the ACTIVE list: Y[act[s]] = X[act[s]] @ W + b  (fp16 out).
// Grid-stride over 32-row slabs; XT = float (layer 1) or __half (layers 2,3).
template <int K, int N, typename XT>
__global__ void k_gemm(const XT* __restrict__ X,
                       const float* __restrict__ W,
                       const float* __restrict__ b) {
    __shared__ float As[32][33];
    __shared__ float Ws[32][N];
    __shared__ int sAct[32];
    const int tid = threadIdx.x;            // 2N threads
    const int tc = tid % (N / 4);
    const int tr = tid / (N / 4);            // 0..7
    const int nact = g_nact;

    for (int s0 = blockIdx.x * 32; s0 < nact; s0 += gridDim.x * 32) {
        if (tid < 32)
            sAct[tid] = (s0 + tid < nact) ? g_act[s0 + tid] : -1;
        __syncthreads();

        float acc[4][4];
#pragma unroll
        for (int i = 0; i < 4; i++)
#pragma unroll
            for (int j = 0; j < 4; j++) acc[i][j] = 0.f;

        for (int k0 = 0; k0 < K; k0 += 32) {
            for (int idx = tid; idx < 32 * 8; idx += 2 * N) {
                int r = idx / 8, c = idx % 8;
                int row = sAct[r];
                float4 vv;
                if (row < 0) {
                    vv = make_float4(0.f, 0.f, 0.f, 0.f);
                } else if (sizeof(XT) == 4) {
                    vv = ((const float4*)X)[row * (K / 4) + k0 / 4 + c];
                } else {
                    uint2 w = ((const uint2*)X)[row * (K / 4) + k0 / 4 + c];
                    float2 p = __half22float2(*(__half2*)&w.x);
                    float2 q = __half22float2(*(__half2*)&w.y);
                    vv = make_float4(p.x, p.y, q.x, q.y);
                }
                As[r][c * 4 + 0] = vv.x; As[r][c * 4 + 1] = vv.y;
                As[r][c * 4 + 2] = vv.z; As[r][c * 4 + 3] = vv.w;
            }
            for (int idx = tid; idx < 32 * N; idx += 2 * N) {
                int r = idx / N, c = idx % N;
                Ws[r][c] = W[(k0 + r) * N + c];
            }
            __syncthreads();
#pragma unroll
            for (int kk = 0; kk < 32; kk++) {
                float a[4];
#pragma unroll
                for (int i = 0; i < 4; i++) a[i] = As[tr * 4 + i][kk];
                float4 wv = *(const float4*)&Ws[kk][tc * 4];
#pragma unroll
                for (int i = 0; i < 4; i++) {
                    acc[i][0] += a[i] * wv.x;
                    acc[i][1] += a[i] * wv.y;
                    acc[i][2] += a[i] * wv.z;
                    acc[i][3] += a[i] * wv.w;
                }
            }
            __syncthreads();
        }
        float b0 = b[tc * 4 + 0], b1 = b[tc * 4 + 1];
        float b2 = b[tc * 4 + 2], b3 = b[tc * 4 + 3];
#pragma unroll
        for (int i = 0; i < 4; i++) {
            int row = sAct[tr * 4 + i];
            if (row >= 0) {
                __half2 h0 = __floats2half2_rn(acc[i][0] + b0, acc[i][1] + b1);
                __half2 h1 = __floats2half2_rn(acc[i][2] + b2, acc[i][3] + b3);
                __half2* dst = (__half2*)&g_Y[(size_t)row * N + tc * 4];
                dst[0] = h0;
                dst[1] = h1;
            }
        }
        __syncthreads();
    }
}

// ---------------------------------------------------------------------------
// Edge aggregation at F_out: AeH[e][:] = Binv[e] * sum_{v in e} Y[v][:]
// Each thread owns 4 halves (one uint2); F/4 threads per row.
template <int F>
__global__ void k_edge_agg() {
    int e = blockIdx.x * blockDim.y + threadIdx.y;
    if (e >= N_E) return;
    const int RPR = F / 4;               // uint2 per row
    int f = threadIdx.x;
    const uint2* __restrict__ Yv = (const uint2*)g_Y;
    int s = g_off_e[e], t = g_off_e[e + 1];
    float acc[4][4];
#pragma unroll
    for (int u = 0; u < 4; u++)
#pragma unroll
        for (int j = 0; j < 4; j++) acc[u][j] = 0.f;
    int m = s;
    for (; m + 4 <= t; m += 4) {
#pragma unroll
        for (int u = 0; u < 4; u++) {
            int idx = g_adj_e[m + u];
            uint2 w = Yv[idx * RPR + f];
            float2 p = __half22float2(*(__half2*)&w.x);
            float2 q = __half22float2(*(__half2*)&w.y);
            acc[u][0] += p.x; acc[u][1] += p.y;
            acc[u][2] += q.x; acc[u][3] += q.y;
        }
    }
    for (; m < t; ++m) {
        int idx = g_adj_e[m];
        uint2 w = Yv[idx * RPR + f];
        float2 p = __half22float2(*(__half2*)&w.x);
        float2 q = __half22float2(*(__half2*)&w.y);
        acc[0][0] += p.x; acc[0][1] += p.y;
        acc[0][2] += q.x; acc[0][3] += q.y;
    }
    float bv = g_Binv[e];
    __half2 h0 = __floats2half2_rn((acc[0][0] + acc[1][0] + acc[2][0] + acc[3][0]) * bv,
                                   (acc[0][1] + acc[1][1] + acc[2][1] + acc[3][1]) * bv);
    __half2 h1 = __floats2half2_rn((acc[0][2] + acc[1][2] + acc[2][2] + acc[3][2]) * bv,
                                   (acc[0][3] + acc[1][3] + acc[2][3] + acc[3][3]) * bv);
    uint2 w;
    w.x = *(unsigned int*)&h0;
    w.y = *(unsigned int*)&h1;
    ((uint2*)g_AeH)[e * RPR + f] = w;
}

// Node aggregation + relu: out[v][:] = relu(Dinv[v] * sum_{e ∋ v} AeH[e][:])
// FINAL=true writes fp32 (d_out, zero-fills inactive rows);
// FINAL=false writes fp16 and skips inactive rows (never gathered).
template <int F, bool FINAL>
__global__ void k_node_agg(void* __restrict__ outp) {
    int v = blockIdx.x * blockDim.y + threadIdx.y;
    if (v >= N_V) return;
    const int RPR = F / 4;
    int f = threadIdx.x;
    int s = g_off_v[v], t = g_off_v[v + 1];
    if (s == t) {
        if (FINAL)
            ((float4*)outp)[v * RPR + f] = make_float4(0.f, 0.f, 0.f, 0.f);
        return;
    }
    const uint2* __restrict__ G = (const uint2*)g_AeH;
    float acc[4][4];
#pragma unroll
    for (int u = 0; u < 4; u++)
#pragma unroll
        for (int j = 0; j < 4; j++) acc[u][j] = 0.f;
    int m = s;
    for (; m + 4 <= t; m += 4) {
#pragma unroll
        for (int u = 0; u < 4; u++) {
            int idx = g_adj_v[m + u];
            uint2 w = G[idx * RPR + f];
            float2 p = __half22float2(*(__half2*)&w.x);
            float2 q = __half22float2(*(__half2*)&w.y);
            acc[u][0] += p.x; acc[u][1] += p.y;
            acc[u][2] += q.x; acc[u][3] += q.y;
        }
    }
    for (; m < t; ++m) {
        int idx = g_adj_v[m];
        uint2 w = G[idx * RPR + f];
        float2 p = __half22float2(*(__half2*)&w.x);
        float2 q = __half22float2(*(__half2*)&w.y);
        acc[0][0] += p.x; acc[0][1] += p.y;
        acc[0][2] += q.x; acc[0][3] += q.y;
    }
    float dv = g_Dinv[v];
    float r0 = fmaxf((acc[0][0] + acc[1][0] + acc[2][0] + acc[3][0]) * dv, 0.f);
    float r1 = fmaxf((acc[0][1] + acc[1][1] + acc[2][1] + acc[3][1]) * dv, 0.f);
    float r2 = fmaxf((acc[0][2] + acc[1][2] + acc[2][2] + acc[3][2]) * dv, 0.f);
    float r3 = fmaxf((acc[0][3] + acc[1][3] + acc[2][3] + acc[3][3]) * dv, 0.f);
    if (FINAL) {
        ((float4*)outp)[v * RPR + f] = make_float4(r0, r1, r2, r3);
    } else {
        __half2 h0 = __floats2half2_rn(r0, r1);
        __half2 h1 = __floats2half2_rn(r2, r3);
        uint2 w;
        w.x = *(unsigned int*)&h0;
        w.y = *(unsigned int*)&h1;
        ((uint2*)outp)[v * RPR + f] = w;
    }
}

// ---------------------------------------------------------------------------
extern "C" void kernel_launch(void* const* d_in, const int* in_sizes, int n_in,
                              void* d_out, int out_size) {
    const float* x  = (const float*)d_in[0];
    const void*  ed = d_in[1];
    const float* w1 = (const float*)d_in[2];
    const float* b1 = (const float*)d_in[3];
    const float* w2 = (const float*)d_in[4];
    const float* b2 = (const float*)d_in[5];
    const float* w3 = (const float*)d_in[6];
    const float* b3 = (const float*)d_in[7];

    void *p_h1 = nullptr, *p_h2 = nullptr;
    cudaGetSymbolAddress(&p_h1, g_h1);
    cudaGetSymbolAddress(&p_h2, g_h2);
    const __half* h1 = (const __half*)p_h1;
    const __half* h2 = (const __half*)p_h2;

    // --- CSR + active-list build ---
    k_prep<<<128, 256>>>((const unsigned int*)ed);
    k_hist<<<782, 256>>>((const int*)ed);
    k_scan<<<SBLK, 1024>>>();
    k_scatter<<<782, 256>>>((const int*)ed);

    const int GEMM_BLKS = 313;   // covers 10016 rows per sweep; loops if more

    // --- Layer 1: 128 -> 128 ---
    k_gemm<128, 128, float><<<GEMM_BLKS, 256>>>(x, w1, b1);
    k_edge_agg<128><<<N_E / 8, dim3(32, 8)>>>();
    k_node_agg<128, false><<<N_V / 8, dim3(32, 8)>>>((void*)h1);

    // --- Layer 2: 128 -> 64 ---
    k_gemm<128, 64, __half><<<GEMM_BLKS, 128>>>(h1, w2, b2);
    k_edge_agg<64><<<N_E / 16, dim3(16, 16)>>>();
    k_node_agg<64, false><<<N_V / 16, dim3(16, 16)>>>((void*)h2);

    // --- Layer 3: 64 -> 32 ---
    k_gemm<64, 32, __half><<<GEMM_BLKS, 64>>>(h2, w3, b3);
    k_edge_agg<32><<<(N_E + 31) / 32, dim3(8, 32)>>>();
    k_node_agg<32, true><<<(N_V + 31) / 32, dim3(8, 32)>>>(d_out);
}